// round 4
// baseline (speedup 1.0000x reference)
#include <cuda_runtime.h>
#include <stdint.h>

#define COLS 16384
#define NTHREADS 512
#define NWARPS (NTHREADS / 32)
#define VEC (COLS / 4 / NTHREADS)   // 8 float4 (32 keys) per thread
#define NBINS 1024                  // 10-bit radix
#define CAP 1024                    // candidate list capacity

// Monotonic float->uint key transform (order-preserving)
__device__ __forceinline__ uint32_t f2k(float f) {
    uint32_t u = __float_as_uint(f);
    return u ^ ((uint32_t)((int32_t)u >> 31) | 0x80000000u);
}
__device__ __forceinline__ float k2f(uint32_t k) {
    uint32_t mask = (~((uint32_t)((int32_t)k >> 31))) | 0x80000000u;
    return __uint_as_float(k ^ mask);
}

// Warp-aggregated histogram add: one atomic per distinct bin per warp step.
// All 32 lanes must be active.
__device__ __forceinline__ void hist_add(int* hist, uint32_t bin) {
    unsigned m = __match_any_sync(0xffffffffu, bin);
    int lane = threadIdx.x & 31;
    if (lane == __ffs(m) - 1) atomicAdd(&hist[bin], __popc(m));
}

// Ballot-aggregated candidate push: one atomicAdd per warp step.
__device__ __forceinline__ void push_cand(int* cand, int* ctr, uint32_t keyv, bool pred) {
    unsigned m = __ballot_sync(0xffffffffu, pred);
    if (m == 0) return;
    int lane = threadIdx.x & 31;
    int leader = __ffs(m) - 1;
    int base = 0;
    if (lane == leader) base = atomicAdd(ctr, __popc(m));
    base = __shfl_sync(0xffffffffu, base, leader);
    if (pred) {
        int pos = base + __popc(m & ((1u << lane) - 1));
        if (pos < CAP) cand[pos] = (int)keyv;
    }
}

// Find highest bin b such that count(bins > b) < kneed <= count(bins >= b).
// ctrl[0]=b, ctrl[1]=count strictly above b, ctrl[2]=hist[b]. Ends with barrier.
__device__ void select_bin(const int* hist, int* warpbuf, int* ctrl, int kneed) {
    const int CH = NBINS / NTHREADS;   // 2
    int t = threadIdx.x, lane = t & 31, w = t >> 5;
    int h[CH];
    int cs = 0;
#pragma unroll
    for (int j = 0; j < CH; j++) { h[j] = hist[t * CH + j]; cs += h[j]; }
    int s = cs;
#pragma unroll
    for (int off = 1; off < 32; off <<= 1) {
        int v = __shfl_down_sync(0xffffffffu, s, off);
        if (lane + off < 32) s += v;
    }
    if (lane == 0) warpbuf[w] = s;
    __syncthreads();
    if (w == 0) {
        int wt = (lane < NWARPS) ? warpbuf[lane] : 0;
        int ws = wt;
#pragma unroll
        for (int off = 1; off < 32; off <<= 1) {
            int v = __shfl_down_sync(0xffffffffu, ws, off);
            if (lane + off < 32) ws += v;
        }
        if (lane < NWARPS) warpbuf[lane] = ws;
    }
    __syncthreads();
    int above = (w < NWARPS - 1) ? warpbuf[w + 1] : 0;
    int S_incl = s + above;
    int S_next = S_incl - cs;
    if (S_incl >= kneed && S_next < kneed) {
        int c = S_next;
#pragma unroll
        for (int j = CH - 1; j >= 0; j--) {
            if (c + h[j] >= kneed) { ctrl[0] = t * CH + j; ctrl[1] = c; ctrl[2] = h[j]; break; }
            c += h[j];
        }
    }
    __syncthreads();
}

__global__ void __launch_bounds__(NTHREADS, 2)
topk_scatter_kernel(const float* __restrict__ x, const int* __restrict__ kp,
                    float* __restrict__ out) {
    __shared__ int hist[NBINS];       // 4 KB
    __shared__ int cand[CAP];         // 4 KB
    __shared__ int warpbuf[NWARPS];
    __shared__ int ctrl[8];

    const int t   = threadIdx.x;
    const int row = blockIdx.x;
    const float4* xr = (const float4*)(x + (size_t)row * COLS);

    // zero hist for pass 1
#pragma unroll
    for (int i = 0; i < NBINS / NTHREADS; i++) hist[t + i * NTHREADS] = 0;
    if (t == 0) ctrl[4] = 0;
    __syncthreads();

    // ---- load row -> registers, histogram top 10 bits (warp-aggregated) ----
    uint4 key[VEC];
#pragma unroll
    for (int i = 0; i < VEC; i++) {
        float4 v = xr[i * NTHREADS + t];
        key[i].x = f2k(v.x); key[i].y = f2k(v.y);
        key[i].z = f2k(v.z); key[i].w = f2k(v.w);
        hist_add(hist, key[i].x >> 22);
        hist_add(hist, key[i].y >> 22);
        hist_add(hist, key[i].z >> 22);
        hist_add(hist, key[i].w >> 22);
    }
    const int K = *kp;
    __syncthreads();

    // ---- pass 1 select: top 10 bits ----
    select_bin(hist, warpbuf, ctrl, K);
    const uint32_t b1 = (uint32_t)ctrl[0];
    int kneed = K - ctrl[1];
    __syncthreads();

    // zero hist for pass 2
#pragma unroll
    for (int i = 0; i < NBINS / NTHREADS; i++) hist[t + i * NTHREADS] = 0;
    __syncthreads();

    // ---- gather candidates (top10 == b1) from regs + pass-2 histogram ----
#pragma unroll
    for (int i = 0; i < VEC; i++) {
        bool px = (key[i].x >> 22) == b1;
        bool py = (key[i].y >> 22) == b1;
        bool pz = (key[i].z >> 22) == b1;
        bool pw = (key[i].w >> 22) == b1;
        if (px) atomicAdd(&hist[(key[i].x >> 12) & 0x3FF], 1);
        if (py) atomicAdd(&hist[(key[i].y >> 12) & 0x3FF], 1);
        if (pz) atomicAdd(&hist[(key[i].z >> 12) & 0x3FF], 1);
        if (pw) atomicAdd(&hist[(key[i].w >> 12) & 0x3FF], 1);
        push_cand(cand, &ctrl[4], key[i].x, px);
        push_cand(cand, &ctrl[4], key[i].y, py);
        push_cand(cand, &ctrl[4], key[i].z, pz);
        push_cand(cand, &ctrl[4], key[i].w, pw);
    }
    __syncthreads();
    const bool use_full = (ctrl[4] > CAP);
    const int cnt = use_full ? 0 : ctrl[4];

    // ---- pass 2 select: bits [21:12] ----
    select_bin(hist, warpbuf, ctrl, kneed);
    const uint32_t b2 = (uint32_t)ctrl[0];
    kneed -= ctrl[1];
    const uint32_t top20 = (b1 << 10) | b2;
    __syncthreads();

    // zero hist for pass 3
#pragma unroll
    for (int i = 0; i < NBINS / NTHREADS; i++) hist[t + i * NTHREADS] = 0;
    __syncthreads();

    // ---- pass 3 histogram: bits [11:2] over candidates (or reg fallback) ----
    if (!use_full) {
        for (int e = t; e < cnt; e += NTHREADS) {
            uint32_t kv = (uint32_t)cand[e];
            if ((kv >> 12) == top20) atomicAdd(&hist[(kv >> 2) & 0x3FF], 1);
        }
    } else {
#pragma unroll
        for (int i = 0; i < VEC; i++) {
            if ((key[i].x >> 12) == top20) atomicAdd(&hist[(key[i].x >> 2) & 0x3FF], 1);
            if ((key[i].y >> 12) == top20) atomicAdd(&hist[(key[i].y >> 2) & 0x3FF], 1);
            if ((key[i].z >> 12) == top20) atomicAdd(&hist[(key[i].z >> 2) & 0x3FF], 1);
            if ((key[i].w >> 12) == top20) atomicAdd(&hist[(key[i].w >> 2) & 0x3FF], 1);
        }
    }
    __syncthreads();
    select_bin(hist, warpbuf, ctrl, kneed);
    const uint32_t b3 = (uint32_t)ctrl[0];
    kneed -= ctrl[1];
    const uint32_t top30 = (top20 << 10) | b3;
    __syncthreads();

    // ---- pass 4: final 2 bits (4 bins) ----
    if (t < 4) hist[t] = 0;
    __syncthreads();
    if (!use_full) {
        for (int e = t; e < cnt; e += NTHREADS) {
            uint32_t kv = (uint32_t)cand[e];
            if ((kv >> 2) == top30) atomicAdd(&hist[kv & 3], 1);
        }
    } else {
#pragma unroll
        for (int i = 0; i < VEC; i++) {
            if ((key[i].x >> 2) == top30) atomicAdd(&hist[key[i].x & 3], 1);
            if ((key[i].y >> 2) == top30) atomicAdd(&hist[key[i].y & 3], 1);
            if ((key[i].z >> 2) == top30) atomicAdd(&hist[key[i].z & 3], 1);
            if ((key[i].w >> 2) == top30) atomicAdd(&hist[key[i].w & 3], 1);
        }
    }
    __syncthreads();
    if (t == 0) {
        int c = 0;
        for (int b = 3; b >= 0; b--) {
            int h = hist[b];
            if (c + h >= kneed) { ctrl[0] = b; ctrl[1] = c; ctrl[2] = h; break; }
            c += h;
        }
    }
    __syncthreads();
    const uint32_t b4 = (uint32_t)ctrl[0];
    const int cnt_eq = ctrl[2];
    const int needed_eq = kneed - ctrl[1];
    const uint32_t T = (top30 << 2) | b4;       // exact k-th largest key

    // ---- deterministic tie-break (rare): keep needed_eq LOWEST column indices ----
    int idx_cut = COLS;
    if (needed_eq < cnt_eq) {
        __syncthreads();
        if (t == 0) ctrl[5] = 0;
        __syncthreads();
#pragma unroll
        for (int i = 0; i < VEC; i++) {
            int base = 4 * (i * NTHREADS + t);
            if (key[i].x == T) { int p = atomicAdd(&ctrl[5], 1); if (p < CAP) cand[p] = base + 0; }
            if (key[i].y == T) { int p = atomicAdd(&ctrl[5], 1); if (p < CAP) cand[p] = base + 1; }
            if (key[i].z == T) { int p = atomicAdd(&ctrl[5], 1); if (p < CAP) cand[p] = base + 2; }
            if (key[i].w == T) { int p = atomicAdd(&ctrl[5], 1); if (p < CAP) cand[p] = base + 3; }
        }
        __syncthreads();
        int tc = ctrl[5] < CAP ? ctrl[5] : CAP;
        for (int e = t; e < tc; e += NTHREADS) {
            int v = cand[e];
            int r = 0;
            for (int q = 0; q < tc; q++) r += (cand[q] < v);
            if (r == needed_eq - 1) ctrl[3] = v;
        }
        __syncthreads();
        idx_cut = ctrl[3];
    }

    // ---- write pass: dense output from regs, float4 streaming stores ----
    float4* outr = (float4*)(out + (size_t)row * COLS);
#pragma unroll
    for (int i = 0; i < VEC; i++) {
        int base = 4 * (i * NTHREADS + t);
        float4 o;
        o.x = (key[i].x > T || (key[i].x == T && base + 0 <= idx_cut)) ? k2f(key[i].x) : 0.0f;
        o.y = (key[i].y > T || (key[i].y == T && base + 1 <= idx_cut)) ? k2f(key[i].y) : 0.0f;
        o.z = (key[i].z > T || (key[i].z == T && base + 2 <= idx_cut)) ? k2f(key[i].z) : 0.0f;
        o.w = (key[i].w > T || (key[i].w == T && base + 3 <= idx_cut)) ? k2f(key[i].w) : 0.0f;
        __stcs(&outr[i * NTHREADS + t], o);
    }
}

extern "C" void kernel_launch(void* const* d_in, const int* in_sizes, int n_in,
                              void* d_out, int out_size) {
    const float* x  = (const float*)d_in[0];
    const int*   kp = (const int*)d_in[1];
    float*       out = (float*)d_out;

    const int rows = in_sizes[0] / COLS;
    topk_scatter_kernel<<<rows, NTHREADS>>>(x, kp, out);
}

// round 5
// speedup vs baseline: 1.8847x; 1.8847x over previous
#include <cuda_runtime.h>
#include <stdint.h>

#define COLS 16384
#define NTHREADS 512
#define NWARPS (NTHREADS / 32)
#define VEC (COLS / 4 / NTHREADS)   // 8 float4 per thread
#define NBINS 1024
#define CAP 2048                    // candidate capacity (expected ~512)

// Monotonic float->uint key transform (order-preserving)
__device__ __forceinline__ uint32_t f2k(float f) {
    uint32_t u = __float_as_uint(f);
    return u ^ ((uint32_t)((int32_t)u >> 31) | 0x80000000u);
}
__device__ __forceinline__ float k2f(uint32_t k) {
    uint32_t mask = (~((uint32_t)((int32_t)k >> 31))) | 0x80000000u;
    return __uint_as_float(k ^ mask);
}

// Ballot-aggregated candidate push: one atomicAdd per warp step.
__device__ __forceinline__ void push2(uint32_t* ckey, int* cidx, int* ctr,
                                      uint32_t key, int idx, bool pred) {
    unsigned m = __ballot_sync(0xffffffffu, pred);
    if (m == 0) return;
    int lane = threadIdx.x & 31;
    int leader = __ffs(m) - 1;
    int base = 0;
    if (lane == leader) base = atomicAdd(ctr, __popc(m));
    base = __shfl_sync(0xffffffffu, base, leader);
    if (pred) {
        int pos = base + __popc(m & ((1u << lane) - 1));
        if (pos < CAP) { ckey[pos] = key; cidx[pos] = idx; }
    }
}

// Find highest bin b: count(bins > b) < kneed <= count(bins >= b).
// ctrl[0]=b, ctrl[1]=count strictly above b, ctrl[2]=hist[b]. Ends with barrier.
__device__ void select_bin(const int* hist, int* warpbuf, int* ctrl, int kneed) {
    const int CH = NBINS / NTHREADS;   // 2
    int t = threadIdx.x, lane = t & 31, w = t >> 5;
    int h[CH];
    int cs = 0;
#pragma unroll
    for (int j = 0; j < CH; j++) { h[j] = hist[t * CH + j]; cs += h[j]; }
    int s = cs;
#pragma unroll
    for (int off = 1; off < 32; off <<= 1) {
        int v = __shfl_down_sync(0xffffffffu, s, off);
        if (lane + off < 32) s += v;
    }
    if (lane == 0) warpbuf[w] = s;
    __syncthreads();
    if (w == 0) {
        int wt = (lane < NWARPS) ? warpbuf[lane] : 0;
        int ws = wt;
#pragma unroll
        for (int off = 1; off < 32; off <<= 1) {
            int v = __shfl_down_sync(0xffffffffu, ws, off);
            if (lane + off < 32) ws += v;
        }
        if (lane < NWARPS) warpbuf[lane] = ws;
    }
    __syncthreads();
    int above = (w < NWARPS - 1) ? warpbuf[w + 1] : 0;
    int S_incl = s + above;
    int S_next = S_incl - cs;
    if (S_incl >= kneed && S_next < kneed) {
        int c = S_next;
#pragma unroll
        for (int j = CH - 1; j >= 0; j--) {
            if (c + h[j] >= kneed) { ctrl[0] = t * CH + j; ctrl[1] = c; ctrl[2] = h[j]; break; }
            c += h[j];
        }
    }
    __syncthreads();
}

__global__ void __launch_bounds__(NTHREADS)
topk_scatter_kernel(const float* __restrict__ x, const int* __restrict__ kp,
                    float* __restrict__ out) {
    __shared__ uint32_t ckey[CAP];      // 8 KB
    __shared__ int      cidx[CAP];      // 8 KB
    __shared__ int      hist[NBINS];    // 4 KB
    __shared__ int      warpbuf[NWARPS];
    __shared__ int      sctrl[8];
    __shared__ unsigned mmx[2];

    const int t   = threadIdx.x;
    const int lane = t & 31;
    const int w    = t >> 5;
    const int row = blockIdx.x;
    const float4* xr = (const float4*)(x + (size_t)row * COLS);
    float* outrow = out + (size_t)row * COLS;
    const int K = *kp;

    // ---- candidate scan with fixed pivot; binary-search fallback keeps it exact ----
    uint32_t lo = 0u, hi = 0xFFFFFFFFu;
    uint32_t pivot = f2k(1.8627f);      // ~1/32 quantile of N(0,1): E[cands]=512
    int cnt = 0;
    bool zero_done = false;
    bool degen = false;

    for (int iter = 0; iter < 48; iter++) {
        if (t == 0) sctrl[4] = 0;
        __syncthreads();
        float4 v[VEC];
#pragma unroll
        for (int i = 0; i < VEC; i++) v[i] = xr[i * NTHREADS + t];    // batched LDG.128
#pragma unroll
        for (int i = 0; i < VEC; i++) {
            int base = 4 * (i * NTHREADS + t);
            uint32_t kx = f2k(v[i].x), ky = f2k(v[i].y);
            uint32_t kz = f2k(v[i].z), kw = f2k(v[i].w);
            push2(ckey, cidx, &sctrl[4], kx, base + 0, kx > pivot);
            push2(ckey, cidx, &sctrl[4], ky, base + 1, ky > pivot);
            push2(ckey, cidx, &sctrl[4], kz, base + 2, kz > pivot);
            push2(ckey, cidx, &sctrl[4], kw, base + 3, kw > pivot);
            if (!zero_done)
                __stcs((float4*)outrow + i * NTHREADS + t, make_float4(0.f, 0.f, 0.f, 0.f));
        }
        __syncthreads();
        zero_done = true;
        cnt = sctrl[4];
        if (degen) break;                          // rescan at pivot==T complete
        if (cnt >= K && cnt <= CAP) break;         // fast path (always on this data)
        if (cnt < K) hi = pivot; else lo = pivot;
        if (hi - lo <= 1u) { degen = true; pivot = hi; continue; }
        pivot = lo + ((hi - lo) >> 1);
    }

    if (degen) {
        // Interval collapsed: T = pivot(=hi); candidates are exactly keys > T, cnt < K.
        const uint32_t T = pivot;
        const int needed_eq = K - cnt;
        for (int e = t; e < cnt; e += NTHREADS) outrow[cidx[e]] = k2f(ckey[e]);
        // ordered scan: keep first needed_eq ties by column index
        if (t == 0) sctrl[6] = 0;
        __syncthreads();
        const float* xrow = x + (size_t)row * COLS;
        for (int seg = 0; seg < COLS / NTHREADS; seg++) {
            int idx = seg * NTHREADS + t;
            bool tie = (f2k(xrow[idx]) == T);
            unsigned m = __ballot_sync(0xffffffffu, tie);
            int wrank = __popc(m & ((1u << lane) - 1));
            if (lane == 0) warpbuf[w] = __popc(m);
            __syncthreads();
            int base = 0;
            for (int j = 0; j < w; j++) base += warpbuf[j];
            int grank = sctrl[6] + base + wrank;
            if (tie && grank < needed_eq) outrow[idx] = k2f(T);
            __syncthreads();
            if (t == 0) {
                int s = 0;
                for (int j = 0; j < NWARPS; j++) s += warpbuf[j];
                sctrl[6] += s;
            }
            __syncthreads();
        }
        return;
    }

    // ---- exact radix select over cnt in [K, CAP] candidates ----
    // common-prefix compression: select only over differing key bits
    if (t == 0) { mmx[0] = 0xFFFFFFFFu; mmx[1] = 0u; }
    __syncthreads();
    {
        uint32_t mn = 0xFFFFFFFFu, mx = 0u;
        for (int e = t; e < cnt; e += NTHREADS) {
            uint32_t kv = ckey[e];
            mn = min(mn, kv); mx = max(mx, kv);
        }
#pragma unroll
        for (int off = 16; off >= 1; off >>= 1) {
            mn = min(mn, __shfl_down_sync(0xffffffffu, mn, off));
            mx = max(mx, __shfl_down_sync(0xffffffffu, mx, off));
        }
        if (lane == 0) { atomicMin(&mmx[0], mn); atomicMax(&mmx[1], mx); }
    }
    __syncthreads();
    const uint32_t mn = mmx[0], mx = mmx[1];

    uint32_t T;
    int needed_eq, cnt_eq;
    if (mn == mx) {
        T = mn; needed_eq = K; cnt_eq = cnt;
    } else {
        int prefix = __clz(mn ^ mx);
        int shift_rem = 32 - prefix;
        uint32_t cur = (prefix == 0) ? 0u : (mn >> shift_rem);
        int kneed = K;
        cnt_eq = 0;
        while (shift_rem > 0) {
            int take = shift_rem > 10 ? 10 : shift_rem;
            shift_rem -= take;
            for (int i = t; i < NBINS; i += NTHREADS) hist[i] = 0;
            __syncthreads();
            uint32_t mask = (1u << take) - 1u;
            for (int e = t; e < cnt; e += NTHREADS) {
                uint32_t kv = ckey[e];
                if ((uint32_t)(((uint64_t)kv) >> (shift_rem + take)) == cur)
                    atomicAdd(&hist[(kv >> shift_rem) & mask], 1);
            }
            __syncthreads();
            select_bin(hist, warpbuf, sctrl, kneed);
            cur = (cur << take) | (uint32_t)sctrl[0];
            kneed -= sctrl[1];
            cnt_eq = sctrl[2];
        }
        T = cur;
        needed_eq = kneed;
    }

    // ---- tie-break (rare): keep needed_eq lowest column indices among key==T ----
    int idx_cut = COLS;
    if (needed_eq < cnt_eq) {
        for (int e = t; e < cnt; e += NTHREADS) {
            if (ckey[e] == T) {
                int v = cidx[e], r = 0;
                for (int q = 0; q < cnt; q++) r += (ckey[q] == T && cidx[q] < v);
                if (r == needed_eq - 1) sctrl[3] = v;
            }
        }
        __syncthreads();
        idx_cut = sctrl[3];
    }

    // ---- scatter winners (zeros already streamed during the scan) ----
    for (int e = t; e < cnt; e += NTHREADS) {
        uint32_t kv = ckey[e];
        if (kv > T || (kv == T && cidx[e] <= idx_cut))
            outrow[cidx[e]] = k2f(kv);
    }
}

extern "C" void kernel_launch(void* const* d_in, const int* in_sizes, int n_in,
                              void* d_out, int out_size) {
    const float* x  = (const float*)d_in[0];
    const int*   kp = (const int*)d_in[1];
    float*       out = (float*)d_out;

    const int rows = in_sizes[0] / COLS;
    topk_scatter_kernel<<<rows, NTHREADS>>>(x, kp, out);
}